// round 7
// baseline (speedup 1.0000x reference)
#include <cuda_runtime.h>
#include <math.h>
#include <stdint.h>

#define Bmax 4
#define C_ 64
#define H_ 128
#define W_ 128
#define O_ 64
#define K_ 9
#define HW_ (H_*W_)

typedef unsigned long long ull;

__device__ __forceinline__ float to_tf32(float v) {
    float r; asm("cvt.rna.tf32.f32 %0, %1;" : "=f"(r) : "f"(v)); return r;
}
__device__ __forceinline__ void mma8(float4 &d, uint32_t a0, uint32_t a1, uint32_t a2, uint32_t a3,
                                     uint32_t b0, uint32_t b1) {
    asm("mma.sync.aligned.m16n8k8.row.col.f32.tf32.tf32.f32 "
        "{%0,%1,%2,%3},{%4,%5,%6,%7},{%8,%9},{%0,%1,%2,%3};"
        : "+f"(d.x), "+f"(d.y), "+f"(d.z), "+f"(d.w)
        : "r"(a0), "r"(a1), "r"(a2), "r"(a3), "r"(b0), "r"(b1));
}
__device__ __forceinline__ ull pack2(float lo, float hi) {
    ull r; asm("mov.b64 %0, {%1, %2};" : "=l"(r) : "f"(lo), "f"(hi)); return r;
}
__device__ __forceinline__ ull mul2(ull a, ull b) {
    ull r; asm("mul.rn.f32x2 %0, %1, %2;" : "=l"(r) : "l"(a), "l"(b)); return r;
}
__device__ __forceinline__ ull fma2v(ull a, ull b, ull c) {
    ull r; asm("fma.rn.f32x2 %0, %1, %2, %3;" : "=l"(r) : "l"(a), "l"(b), "l"(c)); return r;
}

// ---------------- device scratch ----------------
__device__ float g_xn[Bmax*HW_*C_ + 16384];   // NHWC x (fp32), padded
// B fragments, per-thread order:
// g_wt3: [k][ks(8)][j4(4)][t(32)] x float4
__device__ float g_wt3[K_*8*4*32*4];
// g_w1:  [k][ks(8)][j4(2)][t(32)] x float4
__device__ float g_w1[K_*8*2*32*4];

// ---------------- NCHW -> NHWC transpose (vectorized, 2 c-halves per block) ----------------
__global__ __launch_bounds__(256)
void k_transpose(const float* __restrict__ x) {
    __shared__ float t[2][32][33];
    int b  = blockIdx.z;
    int h  = blockIdx.y;
    int w0 = blockIdx.x * 32;
    int tid = threadIdx.x;
    int r  = tid >> 3;        // 0..31
    int q  = tid & 7;         // 0..7
    float4 v0 = *(const float4*)(x + ((size_t)(b*C_ + r     )*H_ + h)*W_ + w0 + q*4);
    float4 v1 = *(const float4*)(x + ((size_t)(b*C_ + 32 + r)*H_ + h)*W_ + w0 + q*4);
    t[0][r][q*4] = v0.x; t[0][r][q*4+1] = v0.y; t[0][r][q*4+2] = v0.z; t[0][r][q*4+3] = v0.w;
    t[1][r][q*4] = v1.x; t[1][r][q*4+1] = v1.y; t[1][r][q*4+2] = v1.z; t[1][r][q*4+3] = v1.w;
    __syncthreads();
    float4 o0, o1;
    o0.x = t[0][q*4][r]; o0.y = t[0][q*4+1][r]; o0.z = t[0][q*4+2][r]; o0.w = t[0][q*4+3][r];
    o1.x = t[1][q*4][r]; o1.y = t[1][q*4+1][r]; o1.z = t[1][q*4+2][r]; o1.w = t[1][q*4+3][r];
    float* dst = g_xn + ((size_t)(b*H_ + h)*W_ + w0 + r)*C_;
    *(float4*)(dst + q*4)      = o0;
    *(float4*)(dst + 32 + q*4) = o1;
}

// ---------------- weight repack into mma fragment order ----------------
__global__ void k_repack(const float* __restrict__ wgt, const float* __restrict__ omw) {
    int f = blockIdx.x*256 + threadIdx.x;
    if (f < K_*4096) {                    // main weights
        int q  = f & 3;
        int t  = (f >> 2) & 31;
        int j4 = (f >> 7) & 3;
        int ks = (f >> 9) & 7;
        int k  = f >> 12;
        int j  = 2*j4 + (q >> 1);
        int c  = ks*8 + (t & 3) + (q & 1)*4;
        int o  = j*8 + (t >> 2);
        g_wt3[f] = to_tf32(wgt[(o*C_ + c)*K_ + k]);
    } else if (f < K_*4096 + K_*2048) {   // om weights
        int f2 = f - K_*4096;
        int q  = f2 & 3;
        int t  = (f2 >> 2) & 31;
        int j4 = (f2 >> 7) & 1;
        int ks = (f2 >> 8) & 7;
        int k  = f2 >> 11;
        int j  = 2*j4 + (q >> 1);
        int c  = ks*8 + (t & 3) + (q & 1)*4;
        int oc = j*8 + (t >> 2);
        g_w1[f2] = (oc < 27) ? to_tf32(omw[(oc*C_ + c)*K_ + k]) : 0.f;
    }
}

// ---------------- fused DCN: one block per (b, h) output row ----------------
// smem byte layout (63 KB -> 3 CTAs/SM)
#define SM_XS  0        // 35360 B : A tile [130 px][68 c] ; om_s [128][34] unions here
#define SM_SW  35360    // 18432 B : float4[9][128] corner weights
#define SM_I0  53792    // 4608  B : int[9][128]
#define SM_DD  58400    // 4608  B : int[9][128]
#define SM_TOT 63008

__global__ __launch_bounds__(256, 3)
void k_dcn(const float* __restrict__ bias, const float* __restrict__ om_bias,
           float* __restrict__ out) {
    extern __shared__ char sm[];
    float*  xs   = (float*)(sm + SM_XS);
    float*  om_s = (float*)(sm + SM_XS);   // union: phase-1 A data dead by then
    float4* s_w  = (float4*)(sm + SM_SW);
    int*    s_i0 = (int*)(sm + SM_I0);
    int*    s_d  = (int*)(sm + SM_DD);

    const int tid  = threadIdx.x;
    const int lane = tid & 31;
    const int w    = tid >> 5;
    const int tg   = lane >> 2;
    const int tig  = lane & 3;
    const int h    = blockIdx.x;
    const int b    = blockIdx.y;
    const int row0 = w*16 + tg;
    const float* xb = g_xn + (size_t)b*HW_*C_;

    // ---------- Phase 1: offset/mask conv (128px x 32oc x 576), 3 row-stagings ----------
    float4 acc1[4];
#pragma unroll
    for (int j = 0; j < 4; j++) acc1[j] = make_float4(0.f, 0.f, 0.f, 0.f);

    for (int ky = 0; ky < 3; ky++) {
        int yy = h + ky - 1;
        // stage input row: xs[r][c], r = xx+1, xx in [-1,128]
        for (int e = tid; e < 2080; e += 256) {
            int c4 = e & 15, r = e >> 4;
            int xx = r - 1;
            float4 v = make_float4(0.f, 0.f, 0.f, 0.f);
            if (yy >= 0 && yy < H_ && xx >= 0 && xx < W_)
                v = *(const float4*)(xb + ((size_t)yy*W_ + xx)*C_ + c4*4);
            *(float4*)(xs + r*68 + c4*4) = v;        // raw fp32; HMMA truncates to tf32
        }
        __syncthreads();
#pragma unroll
        for (int ks = 0; ks < 8; ks++) {
#pragma unroll
            for (int kx = 0; kx < 3; kx++) {
                int ra = (row0 + kx)*68 + ks*8 + tig;
                uint32_t a0 = __float_as_uint(xs[ra]);
                uint32_t a1 = __float_as_uint(xs[ra + 8*68]);
                uint32_t a2 = __float_as_uint(xs[ra + 4]);
                uint32_t a3 = __float_as_uint(xs[ra + 8*68 + 4]);
                const uint4* gB = (const uint4*)(g_w1 + (size_t)(ky*3 + kx)*2048);
                uint4 bf0 = __ldg(gB + (ks*2 + 0)*32 + lane);
                uint4 bf1 = __ldg(gB + (ks*2 + 1)*32 + lane);
                mma8(acc1[0], a0, a1, a2, a3, bf0.x, bf0.y);
                mma8(acc1[1], a0, a1, a2, a3, bf0.z, bf0.w);
                mma8(acc1[2], a0, a1, a2, a3, bf1.x, bf1.y);
                mma8(acc1[3], a0, a1, a2, a3, bf1.z, bf1.w);
            }
        }
        __syncthreads();
    }

    // ---------- Phase 2a: write om fragments to smem [px][34] (A region, now dead) ----------
#pragma unroll
    for (int j = 0; j < 4; j++) {
        int col = j*8 + tig*2;
        *(float2*)(om_s + row0*34 + col)     = make_float2(acc1[j].x, acc1[j].y);
        *(float2*)(om_s + (row0+8)*34 + col) = make_float2(acc1[j].z, acc1[j].w);
    }
    __syncthreads();

    // ---------- Phase 2b: bilinear sampling prep per (px, k) ----------
    for (int e = tid; e < 1152; e += 256) {
        int px = e & 127, k = e >> 7;
        int ky = k / 3, kx = k - 3*ky;
        float oy = om_s[px*34 + k]      + __ldg(om_bias + k);
        float ox = om_s[px*34 + 9 + k]  + __ldg(om_bias + 9 + k);
        float mz = om_s[px*34 + 18 + k] + __ldg(om_bias + 18 + k);
        float mk = 1.f / (1.f + expf(-mz));
        float pyf = oy + (float)(h - 1 + ky);
        float pxf = ox + (float)(px - 1 + kx);
        float y0f = floorf(pyf), x0f = floorf(pxf);
        float ly = pyf - y0f, lx = pxf - x0f;
        int y0 = (int)y0f, x0 = (int)x0f;
        bool vy0 = (y0 >= 0)   & (y0 < H_);
        bool vy1 = (y0 >= -1)  & (y0 < H_-1);
        bool vx0 = (x0 >= 0)   & (x0 < W_);
        bool vx1 = (x0 >= -1)  & (x0 < W_-1);
        float w00 = (1.f-ly)*(1.f-lx)*mk * (float)(vy0 & vx0);
        float w01 = (1.f-ly)*lx*mk       * (float)(vy0 & vx1);
        float w10 = ly*(1.f-lx)*mk       * (float)(vy1 & vx0);
        float w11 = ly*lx*mk             * (float)(vy1 & vx1);
        int cy0 = min(max(y0, 0), H_-1),   cx0 = min(max(x0, 0), W_-1);
        int cy1 = min(max(y0+1, 0), H_-1), cx1 = min(max(x0+1, 0), W_-1);
        s_w[e]  = make_float4(w00, w01, w10, w11);
        s_i0[e] = cy0*W_ + cx0;
        s_d[e]  = (cx1 - cx0) | (((cy1 - cy0)*W_) << 16);
    }
    __syncthreads();

    // ---------- Phase 3: main DCN (128px x 64o x 576) ----------
    float4 acc[8];
#pragma unroll
    for (int j = 0; j < 8; j++) acc[j] = make_float4(0.f, 0.f, 0.f, 0.f);

    for (int k = 0; k < K_; k++) {
        // stage A: bilinear-sampled values (packed f32x2 math)
        for (int e = tid; e < 2048; e += 256) {
            int c4 = e & 15, px = e >> 4;
            int se = k*128 + px;
            float4 wv = s_w[se];
            int i0 = s_i0[se];
            int d  = s_d[se];
            int dx  = d & 0xffff;
            int dyw = d >> 16;
            const float* p00 = xb + (size_t)i0*C_ + c4*4;
            ulonglong2 A  = *(const ulonglong2*)(p00);
            ulonglong2 Bb = *(const ulonglong2*)(p00 + dx*C_);
            ulonglong2 Cc = *(const ulonglong2*)(p00 + dyw*C_);
            ulonglong2 Dd = *(const ulonglong2*)(p00 + (size_t)(dyw+dx)*C_);
            ull w00p = pack2(wv.x, wv.x);
            ull w01p = pack2(wv.y, wv.y);
            ull w10p = pack2(wv.z, wv.z);
            ull w11p = pack2(wv.w, wv.w);
            ull r0 = fma2v(w11p, Dd.x, fma2v(w10p, Cc.x, fma2v(w01p, Bb.x, mul2(w00p, A.x))));
            ull r1 = fma2v(w11p, Dd.y, fma2v(w10p, Cc.y, fma2v(w01p, Bb.y, mul2(w00p, A.y))));
            ulonglong2 rr; rr.x = r0; rr.y = r1;
            *(ulonglong2*)(xs + px*68 + c4*4) = rr;
        }
        __syncthreads();
        const uint4* gB = (const uint4*)(g_wt3 + k*4096);
#pragma unroll
        for (int ks = 0; ks < 8; ks++) {
            int ra = row0*68 + ks*8 + tig;
            uint32_t a0 = __float_as_uint(xs[ra]);
            uint32_t a1 = __float_as_uint(xs[ra + 8*68]);
            uint32_t a2 = __float_as_uint(xs[ra + 4]);
            uint32_t a3 = __float_as_uint(xs[ra + 8*68 + 4]);
#pragma unroll
            for (int j4 = 0; j4 < 4; j4++) {
                uint4 bf = __ldg(gB + (ks*4 + j4)*32 + lane);
                mma8(acc[j4*2],     a0, a1, a2, a3, bf.x, bf.y);
                mma8(acc[j4*2 + 1], a0, a1, a2, a3, bf.z, bf.w);
            }
        }
        __syncthreads();
    }

    // ---------- Epilogue: NCHW store + bias ----------
#pragma unroll
    for (int j = 0; j < 8; j++) {
        int o = j*8 + tig*2;
        float b0v = __ldg(bias + o);
        float b1v = __ldg(bias + o + 1);
        size_t base0 = (((size_t)b*O_ + o    )*H_ + h)*W_;
        size_t base1 = (((size_t)b*O_ + o + 1)*H_ + h)*W_;
        out[base0 + row0]     = acc[j].x + b0v;
        out[base1 + row0]     = acc[j].y + b1v;
        out[base0 + row0 + 8] = acc[j].z + b0v;
        out[base1 + row0 + 8] = acc[j].w + b1v;
    }
}

extern "C" void kernel_launch(void* const* d_in, const int* in_sizes, int n_in,
                              void* d_out, int out_size) {
    const float* x         = (const float*)d_in[0];
    const float* weight    = (const float*)d_in[1];
    const float* bias      = (const float*)d_in[2];
    const float* om_weight = (const float*)d_in[3];
    const float* om_bias   = (const float*)d_in[4];
    float* out = (float*)d_out;

    int B = in_sizes[0] / (C_*H_*W_);
    if (B < 1) B = 1;
    if (B > Bmax) B = Bmax;

    cudaFuncSetAttribute(k_dcn, cudaFuncAttributeMaxDynamicSharedMemorySize, SM_TOT);

    k_transpose<<<dim3(W_/32, H_, B), 256>>>(x);
    int nrep = K_*4096 + K_*2048;
    k_repack<<<(nrep + 255)/256, 256>>>(weight, om_weight);
    k_dcn<<<dim3(H_, B), 256, SM_TOT>>>(bias, om_bias, out);
}

// round 8
// speedup vs baseline: 1.4151x; 1.4151x over previous
#include <cuda_runtime.h>
#include <math.h>
#include <stdint.h>

#define Bmax 4
#define C_ 64
#define H_ 128
#define W_ 128
#define O_ 64
#define K_ 9
#define HW_ (H_*W_)

typedef unsigned long long ull;

__device__ __forceinline__ uint32_t cvt_h2(float hi, float lo) {
    uint32_t r; asm("cvt.rn.f16x2.f32 %0, %1, %2;" : "=r"(r) : "f"(hi), "f"(lo)); return r;
}
__device__ __forceinline__ void mma16(float4 &d, uint32_t a0, uint32_t a1, uint32_t a2, uint32_t a3,
                                      uint32_t b0, uint32_t b1) {
    asm("mma.sync.aligned.m16n8k16.row.col.f32.f16.f16.f32 "
        "{%0,%1,%2,%3},{%4,%5,%6,%7},{%8,%9},{%0,%1,%2,%3};"
        : "+f"(d.x), "+f"(d.y), "+f"(d.z), "+f"(d.w)
        : "r"(a0), "r"(a1), "r"(a2), "r"(a3), "r"(b0), "r"(b1));
}

// ---------------- device scratch ----------------
__device__ float g_xn[Bmax*HW_*C_ + 16384];   // NHWC x (fp32), padded
// fp16 B fragments, per-thread order (uint2 = {b0,b1} half2 pairs):
__device__ uint2 g_wt3h[K_*4*8*32];           // main: [k][ks(4)][j(8)][t(32)]
__device__ uint2 g_w1h[K_*4*4*32];            // om:   [k][ks(4)][j(4)][t(32)]

// ---------------- NCHW -> NHWC transpose (vectorized, 2 c-halves per block) ----------------
__global__ __launch_bounds__(256)
void k_transpose(const float* __restrict__ x) {
    __shared__ float t[2][32][33];
    int b  = blockIdx.z;
    int h  = blockIdx.y;
    int w0 = blockIdx.x * 32;
    int tid = threadIdx.x;
    int r  = tid >> 3;
    int q  = tid & 7;
    float4 v0 = *(const float4*)(x + ((size_t)(b*C_ + r     )*H_ + h)*W_ + w0 + q*4);
    float4 v1 = *(const float4*)(x + ((size_t)(b*C_ + 32 + r)*H_ + h)*W_ + w0 + q*4);
    t[0][r][q*4] = v0.x; t[0][r][q*4+1] = v0.y; t[0][r][q*4+2] = v0.z; t[0][r][q*4+3] = v0.w;
    t[1][r][q*4] = v1.x; t[1][r][q*4+1] = v1.y; t[1][r][q*4+2] = v1.z; t[1][r][q*4+3] = v1.w;
    __syncthreads();
    float4 o0, o1;
    o0.x = t[0][q*4][r]; o0.y = t[0][q*4+1][r]; o0.z = t[0][q*4+2][r]; o0.w = t[0][q*4+3][r];
    o1.x = t[1][q*4][r]; o1.y = t[1][q*4+1][r]; o1.z = t[1][q*4+2][r]; o1.w = t[1][q*4+3][r];
    float* dst = g_xn + ((size_t)(b*H_ + h)*W_ + w0 + r)*C_;
    *(float4*)(dst + q*4)      = o0;
    *(float4*)(dst + 32 + q*4) = o1;
}

// ---------------- weight repack into fp16 mma fragment order ----------------
__global__ void k_repack(const float* __restrict__ wgt, const float* __restrict__ omw) {
    int f = blockIdx.x*256 + threadIdx.x;
    if (f < K_*4*8*32) {                  // main weights
        int t  = f & 31;
        int j  = (f >> 5) & 7;
        int ks = (f >> 8) & 3;
        int k  = f >> 10;
        int o  = j*8 + (t >> 2);
        int c0 = ks*16 + 2*(t & 3);
        const float* wb = wgt + (size_t)o*C_*K_;
        uint32_t b0 = cvt_h2(wb[(c0+1)*K_ + k], wb[c0*K_ + k]);
        uint32_t b1 = cvt_h2(wb[(c0+9)*K_ + k], wb[(c0+8)*K_ + k]);
        g_wt3h[f] = make_uint2(b0, b1);
    } else if (f < K_*4*8*32 + K_*4*4*32) {
        int f2 = f - K_*4*8*32;
        int t  = f2 & 31;
        int j  = (f2 >> 5) & 3;
        int ks = (f2 >> 7) & 3;
        int k  = f2 >> 9;
        int oc = j*8 + (t >> 2);
        int c0 = ks*16 + 2*(t & 3);
        uint32_t b0 = 0, b1 = 0;
        if (oc < 27) {
            const float* wb = omw + (size_t)oc*C_*K_;
            b0 = cvt_h2(wb[(c0+1)*K_ + k], wb[c0*K_ + k]);
            b1 = cvt_h2(wb[(c0+9)*K_ + k], wb[(c0+8)*K_ + k]);
        }
        g_w1h[f2] = make_uint2(b0, b1);
    }
}

// ---------------- fused DCN: one block per (b, h) output row ----------------
// smem byte layout (58.7 KB)
#define SM_XS  0        // 18720 B : A tile half[130 px][72 c] ; om_s float[128][34] unions here
#define SM_B   18720    // 12288 B : B fragments (ph1: 3 taps x 4KB; ph3: 8KB)
#define SM_SW  31008    // 18432 B : float4[9][128] corner weights
#define SM_I0  49440    // 4608  B : int[9][128]
#define SM_DD  54048    // 4608  B : int[9][128]
#define SM_TOT 58656

__global__ __launch_bounds__(256, 2)
void k_dcn(const float* __restrict__ bias, const float* __restrict__ om_bias,
           float* __restrict__ out) {
    extern __shared__ char sm[];
    uint32_t* xsu   = (uint32_t*)(sm + SM_XS);   // A tile, u32 view (row stride 36)
    uint2*    xsu2  = (uint2*)(sm + SM_XS);      // A tile, uint2 view (row stride 18)
    float*    om_s  = (float*)(sm + SM_XS);      // union: phase-1 A dead by phase 2a
    uint2*    bB    = (uint2*)(sm + SM_B);
    uint4*    bB4   = (uint4*)(sm + SM_B);
    float4*   s_w   = (float4*)(sm + SM_SW);
    int*      s_i0  = (int*)(sm + SM_I0);
    int*      s_d   = (int*)(sm + SM_DD);

    const int tid  = threadIdx.x;
    const int lane = tid & 31;
    const int w    = tid >> 5;
    const int tg   = lane >> 2;
    const int tig  = lane & 3;
    const int h    = blockIdx.x;
    const int b    = blockIdx.y;
    const int row0 = w*16 + tg;
    const float* xb = g_xn + (size_t)b*HW_*C_;

    // ---------- Phase 1: offset/mask conv (128px x 32oc x 576), 3 row-stagings ----------
    float4 acc1[4];
#pragma unroll
    for (int j = 0; j < 4; j++) acc1[j] = make_float4(0.f, 0.f, 0.f, 0.f);

    for (int ky = 0; ky < 3; ky++) {
        int yy = h + ky - 1;
        // stage input row (fp16): xsu2[r][c4], r = xx+1, xx in [-1,128]
        for (int e = tid; e < 2080; e += 256) {
            int c4 = e & 15, r = e >> 4;
            int xx = r - 1;
            float4 v = make_float4(0.f, 0.f, 0.f, 0.f);
            if (yy >= 0 && yy < H_ && xx >= 0 && xx < W_)
                v = *(const float4*)(xb + ((size_t)yy*W_ + xx)*C_ + c4*4);
            xsu2[r*18 + c4] = make_uint2(cvt_h2(v.y, v.x), cvt_h2(v.w, v.z));
        }
        // stage B for 3 kx taps: 3 x 512 uint2 = 768 uint4
        {
            const uint4* src = (const uint4*)(g_w1h + (size_t)ky*3*512);
            for (int e = tid; e < 768; e += 256) bB4[e] = src[e];
        }
        __syncthreads();
#pragma unroll
        for (int ks = 0; ks < 4; ks++) {
#pragma unroll
            for (int kx = 0; kx < 3; kx++) {
                int ra = (row0 + kx)*36 + ks*8 + tig;
                uint32_t a0 = xsu[ra];
                uint32_t a1 = xsu[ra + 8*36];
                uint32_t a2 = xsu[ra + 4];
                uint32_t a3 = xsu[ra + 8*36 + 4];
#pragma unroll
                for (int j = 0; j < 4; j++) {
                    uint2 bf = bB[kx*512 + (ks*4 + j)*32 + lane];
                    mma16(acc1[j], a0, a1, a2, a3, bf.x, bf.y);
                }
            }
        }
        __syncthreads();
    }

    // ---------- Phase 2a: write om fragments to smem [px][34] ----------
#pragma unroll
    for (int j = 0; j < 4; j++) {
        int col = j*8 + tig*2;
        *(float2*)(om_s + row0*34 + col)     = make_float2(acc1[j].x, acc1[j].y);
        *(float2*)(om_s + (row0+8)*34 + col) = make_float2(acc1[j].z, acc1[j].w);
    }
    __syncthreads();

    // ---------- Phase 2b: bilinear sampling prep per (px, k) ----------
    for (int e = tid; e < 1152; e += 256) {
        int px = e & 127, k = e >> 7;
        int ky = k / 3, kx = k - 3*ky;
        float oy = om_s[px*34 + k]      + __ldg(om_bias + k);
        float ox = om_s[px*34 + 9 + k]  + __ldg(om_bias + 9 + k);
        float mz = om_s[px*34 + 18 + k] + __ldg(om_bias + 18 + k);
        float mk = 1.f / (1.f + expf(-mz));
        float pyf = oy + (float)(h - 1 + ky);
        float pxf = ox + (float)(px - 1 + kx);
        float y0f = floorf(pyf), x0f = floorf(pxf);
        float ly = pyf - y0f, lx = pxf - x0f;
        int y0 = (int)y0f, x0 = (int)x0f;
        bool vy0 = (y0 >= 0)   & (y0 < H_);
        bool vy1 = (y0 >= -1)  & (y0 < H_-1);
        bool vx0 = (x0 >= 0)   & (x0 < W_);
        bool vx1 = (x0 >= -1)  & (x0 < W_-1);
        float w00 = (1.f-ly)*(1.f-lx)*mk * (float)(vy0 & vx0);
        float w01 = (1.f-ly)*lx*mk       * (float)(vy0 & vx1);
        float w10 = ly*(1.f-lx)*mk       * (float)(vy1 & vx0);
        float w11 = ly*lx*mk             * (float)(vy1 & vx1);
        int cy0 = min(max(y0, 0), H_-1),   cx0 = min(max(x0, 0), W_-1);
        int cy1 = min(max(y0+1, 0), H_-1), cx1 = min(max(x0+1, 0), W_-1);
        s_w[e]  = make_float4(w00, w01, w10, w11);
        s_i0[e] = cy0*W_ + cx0;
        s_d[e]  = (cx1 - cx0) | (((cy1 - cy0)*W_) << 16);
    }
    __syncthreads();

    // ---------- Phase 3: main DCN (128px x 64o x 576) ----------
    float4 acc[8];
#pragma unroll
    for (int j = 0; j < 8; j++) acc[j] = make_float4(0.f, 0.f, 0.f, 0.f);

    for (int k = 0; k < K_; k++) {
        // stage A: bilinear-sampled values -> fp16
        for (int e = tid; e < 2048; e += 256) {
            int c4 = e & 15, px = e >> 4;
            int se = k*128 + px;
            float4 wv = s_w[se];
            int i0 = s_i0[se];
            int d  = s_d[se];
            int dx  = d & 0xffff;
            int dyw = d >> 16;
            const float* p00 = xb + (size_t)i0*C_ + c4*4;
            float4 A  = *(const float4*)(p00);
            float4 Bb = *(const float4*)(p00 + dx*C_);
            float4 Cc = *(const float4*)(p00 + dyw*C_);
            float4 Dd = *(const float4*)(p00 + (size_t)(dyw+dx)*C_);
            float r0 = wv.x*A.x + wv.y*Bb.x + wv.z*Cc.x + wv.w*Dd.x;
            float r1 = wv.x*A.y + wv.y*Bb.y + wv.z*Cc.y + wv.w*Dd.y;
            float r2 = wv.x*A.z + wv.y*Bb.z + wv.z*Cc.z + wv.w*Dd.z;
            float r3 = wv.x*A.w + wv.y*Bb.w + wv.z*Cc.w + wv.w*Dd.w;
            xsu2[px*18 + c4] = make_uint2(cvt_h2(r1, r0), cvt_h2(r3, r2));
        }
        // stage B frags: 1024 uint2 = 512 uint4
        {
            const uint4* src = (const uint4*)(g_wt3h + (size_t)k*1024);
            for (int e = tid; e < 512; e += 256) bB4[e] = src[e];
        }
        __syncthreads();
#pragma unroll
        for (int ks = 0; ks < 4; ks++) {
            int ra = row0*36 + ks*8 + tig;
            uint32_t a0 = xsu[ra];
            uint32_t a1 = xsu[ra + 8*36];
            uint32_t a2 = xsu[ra + 4];
            uint32_t a3 = xsu[ra + 8*36 + 4];
#pragma unroll
            for (int j = 0; j < 8; j++) {
                uint2 bf = bB[(ks*8 + j)*32 + lane];
                mma16(acc[j], a0, a1, a2, a3, bf.x, bf.y);
            }
        }
        __syncthreads();
    }

    // ---------- Epilogue: NCHW store + bias ----------
#pragma unroll
    for (int j = 0; j < 8; j++) {
        int o = j*8 + tig*2;
        float b0v = __ldg(bias + o);
        float b1v = __ldg(bias + o + 1);
        size_t base0 = (((size_t)b*O_ + o    )*H_ + h)*W_;
        size_t base1 = (((size_t)b*O_ + o + 1)*H_ + h)*W_;
        out[base0 + row0]     = acc[j].x + b0v;
        out[base1 + row0]     = acc[j].y + b1v;
        out[base0 + row0 + 8] = acc[j].z + b0v;
        out[base1 + row0 + 8] = acc[j].w + b1v;
    }
}

extern "C" void kernel_launch(void* const* d_in, const int* in_sizes, int n_in,
                              void* d_out, int out_size) {
    const float* x         = (const float*)d_in[0];
    const float* weight    = (const float*)d_in[1];
    const float* bias      = (const float*)d_in[2];
    const float* om_weight = (const float*)d_in[3];
    const float* om_bias   = (const float*)d_in[4];
    float* out = (float*)d_out;

    int B = in_sizes[0] / (C_*H_*W_);
    if (B < 1) B = 1;
    if (B > Bmax) B = Bmax;

    cudaFuncSetAttribute(k_dcn, cudaFuncAttributeMaxDynamicSharedMemorySize, SM_TOT);

    k_transpose<<<dim3(W_/32, H_, B), 256>>>(x);
    int nrep = K_*4*8*32 + K_*4*4*32;
    k_repack<<<(nrep + 255)/256, 256>>>(weight, om_weight);
    k_dcn<<<dim3(H_, B), 256, SM_TOT>>>(bias, om_bias, out);
}